// round 6
// baseline (speedup 1.0000x reference)
#include <cuda_runtime.h>
#include <cuda_fp16.h>

typedef unsigned long long u64;
typedef unsigned int u32;

#define NMAX 100000
#define NPAD (NMAX + 128)
#define EMAX 1600000
#define NG   64
#define GTM  128   // rows per GEMM/fused CTA

// ---- device scratch ----
__device__ __half g_ga[NPAD * 64];    // g buffers (double-buffered), fp16
__device__ __half g_gb[NPAD * 64];
__device__ __half g_hbf[NPAD * 64];   // x as fp16 (zero beyond n)
__device__ float  g_psum[NG * 64];    // pooled partial sums
__device__ float  g_dinv[NMAX];
__device__ int    g_cnt[NMAX];
__device__ int    g_rowptr[NMAX + 1];
__device__ int    g_cursor[NMAX];
__device__ int    g_col[EMAX];
__device__ int    g_bsums[1024];
__device__ int    g_gstart[NG];
__device__ int    g_gend[NG];

// ---------------- setup kernels ----------------

__global__ void init_k(int n) {
    int i = blockIdx.x * blockDim.x + threadIdx.x;
    if (i < n) g_cnt[i] = 0;
    if (i < NG) { g_gstart[i] = 0x7fffffff; g_gend[i] = -1; }
    if (i < NG * 64) g_psum[i] = 0.f;
}

// x (fp32) -> g_hbf (fp16)
__global__ void xcvt_k(const float* __restrict__ x, int n64) {
    int i = blockIdx.x * blockDim.x + threadIdx.x;   // 8 elems per thread
    if (i * 8 >= n64) return;
    const float4* xp = (const float4*)(x) + i * 2;
    float4 a = xp[0], b = xp[1];
    __half2 h0 = __floats2half2_rn(a.x, a.y);
    __half2 h1 = __floats2half2_rn(a.z, a.w);
    __half2 h2 = __floats2half2_rn(b.x, b.y);
    __half2 h3 = __floats2half2_rn(b.z, b.w);
    ((uint4*)g_hbf)[i] = make_uint4(*(u32*)&h0, *(u32*)&h1, *(u32*)&h2, *(u32*)&h3);
}

// degree count + graph bounds via sorted-batch boundary detection
__global__ void countb_k(const int* __restrict__ dst, const int* __restrict__ batch,
                         int e, int n) {
    int i = blockIdx.x * blockDim.x + threadIdx.x;
    if (i < e) atomicAdd(&g_cnt[dst[i]], 1);
    if (i < n) {
        int b = batch[i];
        if (i == 0) g_gstart[b] = 0;
        else {
            int pb = batch[i - 1];
            if (pb != b) { g_gstart[b] = i; g_gend[pb] = i - 1; }
        }
        if (i == n - 1) g_gend[b] = n - 1;
    }
}

__global__ void scan1_k(int n) {
    int t = threadIdx.x;
    int i = blockIdx.x * 1024 + t;
    int v = (i < n) ? g_cnt[i] : 0;
    if (i < n) g_dinv[i] = rsqrtf((float)v + 1.0f);
    int x = v;
    #pragma unroll
    for (int o = 1; o < 32; o <<= 1) {
        int y = __shfl_up_sync(0xffffffffu, x, o);
        if ((t & 31) >= o) x += y;
    }
    __shared__ int wsum[32];
    if ((t & 31) == 31) wsum[t >> 5] = x;
    __syncthreads();
    if (t < 32) {
        int y = wsum[t];
        int z = y;
        #pragma unroll
        for (int o = 1; o < 32; o <<= 1) {
            int w = __shfl_up_sync(0xffffffffu, z, o);
            if (t >= o) z += w;
        }
        wsum[t] = z - y;
        if (t == 31) g_bsums[blockIdx.x] = z;
    }
    __syncthreads();
    int excl = (x - v) + wsum[t >> 5];
    if (i < n) g_rowptr[i] = excl;
}

__global__ void scan2_k(int nb) {
    int t = threadIdx.x;
    int v = (t < nb) ? g_bsums[t] : 0;
    int x = v;
    #pragma unroll
    for (int o = 1; o < 32; o <<= 1) {
        int y = __shfl_up_sync(0xffffffffu, x, o);
        if ((t & 31) >= o) x += y;
    }
    __shared__ int wsum[32];
    if ((t & 31) == 31) wsum[t >> 5] = x;
    __syncthreads();
    if (t < 32) {
        int y = wsum[t];
        int z = y;
        #pragma unroll
        for (int o = 1; o < 32; o <<= 1) {
            int w = __shfl_up_sync(0xffffffffu, z, o);
            if (t >= o) z += w;
        }
        wsum[t] = z - y;
    }
    __syncthreads();
    int excl = (x - v) + wsum[t >> 5];
    if (t < nb) g_bsums[t] = excl;
}

__global__ void scan3_k(int n, int etot) {
    int i = blockIdx.x * 1024 + threadIdx.x;
    if (i < n) {
        int v = g_rowptr[i] + g_bsums[blockIdx.x];
        g_rowptr[i] = v;
        g_cursor[i] = v;
    }
    if (i == 0) g_rowptr[n] = etot;
}

__global__ void fill_k(const int* __restrict__ src, const int* __restrict__ dst, int e) {
    int i = blockIdx.x * blockDim.x + threadIdx.x;
    if (i < e) {
        int d = dst[i];
        int p = atomicAdd(&g_cursor[d], 1);
        g_col[p] = src[i];
    }
}

// ---- shared gather: fp32 edge-sum of g rows (half2 lane layout) ----
static __device__ __forceinline__ float2 gather_sum(const __half2* __restrict__ g2,
                                                    int node, int lane) {
    int beg = g_rowptr[node];
    int end = g_rowptr[node + 1];
    float2 acc = __half22float2(g2[(size_t)node * 32 + lane]);   // self term
    int e = beg;
    for (; e + 8 <= end; e += 8) {
        int s0 = __ldg(&g_col[e + 0]);
        int s1 = __ldg(&g_col[e + 1]);
        int s2 = __ldg(&g_col[e + 2]);
        int s3 = __ldg(&g_col[e + 3]);
        int s4 = __ldg(&g_col[e + 4]);
        int s5 = __ldg(&g_col[e + 5]);
        int s6 = __ldg(&g_col[e + 6]);
        int s7 = __ldg(&g_col[e + 7]);
        float2 f0 = __half22float2(g2[(size_t)s0 * 32 + lane]);
        float2 f1 = __half22float2(g2[(size_t)s1 * 32 + lane]);
        float2 f2 = __half22float2(g2[(size_t)s2 * 32 + lane]);
        float2 f3 = __half22float2(g2[(size_t)s3 * 32 + lane]);
        float2 f4 = __half22float2(g2[(size_t)s4 * 32 + lane]);
        float2 f5 = __half22float2(g2[(size_t)s5 * 32 + lane]);
        float2 f6 = __half22float2(g2[(size_t)s6 * 32 + lane]);
        float2 f7 = __half22float2(g2[(size_t)s7 * 32 + lane]);
        acc.x += ((f0.x + f1.x) + (f2.x + f3.x)) + ((f4.x + f5.x) + (f6.x + f7.x));
        acc.y += ((f0.y + f1.y) + (f2.y + f3.y)) + ((f4.y + f5.y) + (f6.y + f7.y));
    }
    for (; e < end; e++) {
        int s = __ldg(&g_col[e]);
        float2 v = __half22float2(g2[(size_t)s * 32 + lane]);
        acc.x += v.x; acc.y += v.y;
    }
    return acc;
}

// ---------------- standalone HFMA2 GEMM (layer 1) ----------------
// CTA: 128 rows x 64 cols, 128 threads; thread: 8 rows x 8 cols. (R5 proven)
__global__ void __launch_bounds__(128, 4) gemm_h2_k(const float* __restrict__ W,
                                                    __half* __restrict__ gout, int n) {
    __shared__ __align__(16) unsigned char sXT[16384];   // 64 k x 128 halves (swizzled)
    __shared__ __align__(16) __half sWh[4096];           // w[k][c]
    __shared__ float sdinv[GTM];

    int t = threadIdx.x;
    int tile0 = blockIdx.x * GTM;

    {
        const float4* W4 = (const float4*)W;
        __half2* wh2 = (__half2*)sWh;
        #pragma unroll
        for (int j = t; j < 1024; j += 128) {
            float4 v = W4[j];
            wh2[2 * j]     = __floats2half2_rn(v.x, v.y);
            wh2[2 * j + 1] = __floats2half2_rn(v.z, v.w);
        }
    }
    if (t < GTM) {
        int r = tile0 + t;
        sdinv[t] = (r < n) ? g_dinv[r] : 0.f;
    }
    {
        int r = t;
        const uint4* hp = (const uint4*)(g_hbf + (size_t)(tile0 + r) * 64);
        int rc = r >> 3, rb = (r & 7) * 2;
        #pragma unroll
        for (int q = 0; q < 8; q++) {
            uint4 v = hp[q];
            __half h[8];
            *(uint4*)h = v;
            #pragma unroll
            for (int j = 0; j < 8; j++) {
                int k = 8 * q + j;
                *(__half*)(sXT + k * 256 + ((rc ^ (k & 15)) << 4) + rb) = h[j];
            }
        }
    }
    __syncthreads();

    int rg = t & 15;
    int cgp = t >> 4;

    float fac[64];
    #pragma unroll
    for (int a = 0; a < 64; a++) fac[a] = 0.f;

    #pragma unroll
    for (int half = 0; half < 2; half++) {
        __half2 acc[32];
        #pragma unroll
        for (int a = 0; a < 32; a++) acc[a] = __floats2half2_rn(0.f, 0.f);

        #pragma unroll 8
        for (int kk = 0; kk < 32; kk++) {
            int k = half * 32 + kk;
            uint4 xv = *(const uint4*)(sXT + k * 256 + ((rg ^ (k & 15)) << 4));
            uint4 wv = *(const uint4*)(sWh + (size_t)k * 64 + cgp * 8);
            __half2 w0 = *(__half2*)&wv.x, w1 = *(__half2*)&wv.y;
            __half2 w2 = *(__half2*)&wv.z, w3 = *(__half2*)&wv.w;
            u32 xw[4] = {xv.x, xv.y, xv.z, xv.w};
            #pragma unroll
            for (int p = 0; p < 4; p++) {
                __half2 xpair = *(__half2*)&xw[p];
                __half2 xlo = __low2half2(xpair);
                __half2 xhi = __high2half2(xpair);
                acc[(2 * p) * 4 + 0] = __hfma2(xlo, w0, acc[(2 * p) * 4 + 0]);
                acc[(2 * p) * 4 + 1] = __hfma2(xlo, w1, acc[(2 * p) * 4 + 1]);
                acc[(2 * p) * 4 + 2] = __hfma2(xlo, w2, acc[(2 * p) * 4 + 2]);
                acc[(2 * p) * 4 + 3] = __hfma2(xlo, w3, acc[(2 * p) * 4 + 3]);
                acc[(2 * p + 1) * 4 + 0] = __hfma2(xhi, w0, acc[(2 * p + 1) * 4 + 0]);
                acc[(2 * p + 1) * 4 + 1] = __hfma2(xhi, w1, acc[(2 * p + 1) * 4 + 1]);
                acc[(2 * p + 1) * 4 + 2] = __hfma2(xhi, w2, acc[(2 * p + 1) * 4 + 2]);
                acc[(2 * p + 1) * 4 + 3] = __hfma2(xhi, w3, acc[(2 * p + 1) * 4 + 3]);
            }
        }
        #pragma unroll
        for (int j = 0; j < 8; j++)
            #pragma unroll
            for (int cp = 0; cp < 4; cp++) {
                float2 f = __half22float2(acc[j * 4 + cp]);
                fac[j * 8 + 2 * cp]     += f.x;
                fac[j * 8 + 2 * cp + 1] += f.y;
            }
    }

    // epilogue: direct global stores (8B per row)
    #pragma unroll
    for (int j = 0; j < 8; j++) {
        int r = 8 * rg + j;
        int node = tile0 + r;
        if (node < n) {
            float di = sdinv[r];
            __half2 o[4];
            #pragma unroll
            for (int cp = 0; cp < 4; cp++)
                o[cp] = __floats2half2_rn(fac[j * 8 + 2 * cp] * di,
                                          fac[j * 8 + 2 * cp + 1] * di);
            ((uint4*)(gout + (size_t)node * 64))[cgp] = *(uint4*)o;
        }
    }
}

// ---------------- fused agg + GEMM ----------------
// Phase 1: 8 warps x 16 nodes gather/agg -> h written transposed into sXT (fp16).
// Phase 2: HFMA2 GEMM 256 threads (8 rows x 4 cols per thread) -> gout.
__global__ void __launch_bounds__(256) agggemm_k(const float* __restrict__ bias,
                                                 const float* __restrict__ W,
                                                 const __half* __restrict__ gin,
                                                 __half* __restrict__ gout, int n) {
    __shared__ __align__(16) unsigned char sXT[16384];
    __shared__ __align__(16) __half sWh[4096];
    __shared__ float sdinv[GTM];

    int t = threadIdx.x;
    int tile0 = blockIdx.x * GTM;

    {
        const float4* W4 = (const float4*)W;
        __half2* wh2 = (__half2*)sWh;
        #pragma unroll
        for (int j = t; j < 1024; j += 256) {
            float4 v = W4[j];
            wh2[2 * j]     = __floats2half2_rn(v.x, v.y);
            wh2[2 * j + 1] = __floats2half2_rn(v.z, v.w);
        }
    }
    if (t < GTM) {
        int r = tile0 + t;
        sdinv[t] = (r < n) ? g_dinv[r] : 0.f;
    }

    // phase 1: agg
    int w = t >> 5, lane = t & 31;
    float2 b = ((const float2*)bias)[lane];
    const __half2* g2 = (const __half2*)gin;
    #pragma unroll 1
    for (int i = 0; i < 16; i++) {
        int r = w * 16 + i;
        int node = tile0 + r;
        if (node >= n) break;
        float2 acc = gather_sum(g2, node, lane);
        float di = g_dinv[node];
        float ox = fmaxf(di * acc.x + b.x, 0.f);
        float oy = fmaxf(di * acc.y + b.y, 0.f);
        __half hx = __float2half_rn(ox), hy = __float2half_rn(oy);
        int rc = r >> 3, rb = (r & 7) * 2;
        int k0 = 2 * lane, k1 = k0 + 1;
        *(__half*)(sXT + k0 * 256 + ((rc ^ (k0 & 15)) << 4) + rb) = hx;
        *(__half*)(sXT + k1 * 256 + ((rc ^ (k1 & 15)) << 4) + rb) = hy;
    }
    __syncthreads();

    // phase 2: GEMM, thread tile 8 rows x 4 cols
    int rg = t & 15;          // rows 8*rg..+7
    int cg = t >> 4;          // cols 4*cg..+3

    float fac[32];
    #pragma unroll
    for (int a = 0; a < 32; a++) fac[a] = 0.f;

    #pragma unroll
    for (int half = 0; half < 2; half++) {
        __half2 acc[16];
        #pragma unroll
        for (int a = 0; a < 16; a++) acc[a] = __floats2half2_rn(0.f, 0.f);

        #pragma unroll 8
        for (int kk = 0; kk < 32; kk++) {
            int k = half * 32 + kk;
            uint4 xv = *(const uint4*)(sXT + k * 256 + ((rg ^ (k & 15)) << 4));
            uint2 wv = *(const uint2*)(sWh + (size_t)k * 64 + cg * 4);
            __half2 w0 = *(__half2*)&wv.x, w1 = *(__half2*)&wv.y;
            u32 xw[4] = {xv.x, xv.y, xv.z, xv.w};
            #pragma unroll
            for (int p = 0; p < 4; p++) {
                __half2 xpair = *(__half2*)&xw[p];
                __half2 xlo = __low2half2(xpair);
                __half2 xhi = __high2half2(xpair);
                acc[(2 * p) * 2 + 0]     = __hfma2(xlo, w0, acc[(2 * p) * 2 + 0]);
                acc[(2 * p) * 2 + 1]     = __hfma2(xlo, w1, acc[(2 * p) * 2 + 1]);
                acc[(2 * p + 1) * 2 + 0] = __hfma2(xhi, w0, acc[(2 * p + 1) * 2 + 0]);
                acc[(2 * p + 1) * 2 + 1] = __hfma2(xhi, w1, acc[(2 * p + 1) * 2 + 1]);
            }
        }
        #pragma unroll
        for (int j = 0; j < 8; j++)
            #pragma unroll
            for (int cp = 0; cp < 2; cp++) {
                float2 f = __half22float2(acc[j * 2 + cp]);
                fac[j * 4 + 2 * cp]     += f.x;
                fac[j * 4 + 2 * cp + 1] += f.y;
            }
    }

    // epilogue: direct stores, 8B per row per thread
    #pragma unroll
    for (int j = 0; j < 8; j++) {
        int r = 8 * rg + j;
        int node = tile0 + r;
        if (node < n) {
            float di = sdinv[r];
            __half2 o0 = __floats2half2_rn(fac[j * 4 + 0] * di, fac[j * 4 + 1] * di);
            __half2 o1 = __floats2half2_rn(fac[j * 4 + 2] * di, fac[j * 4 + 3] * di);
            ((uint2*)(gout + (size_t)node * 64))[cg] = make_uint2(*(u32*)&o0, *(u32*)&o1);
        }
    }
}

// ---------------- fused agg (layer 3) + pool partial sums ----------------
__global__ void __launch_bounds__(256) aggpool_k(const float* __restrict__ bias,
                                                 const int* __restrict__ batch,
                                                 const __half* __restrict__ gin, int n) {
    int t = threadIdx.x;
    int w = t >> 5, lane = t & 31;
    int tile0 = blockIdx.x * GTM;
    float2 b = ((const float2*)bias)[lane];
    const __half2* g2 = (const __half2*)gin;

    float2 ps = make_float2(0.f, 0.f);
    int curg = -1;
    #pragma unroll 1
    for (int i = 0; i < 16; i++) {
        int node = tile0 + w * 16 + i;
        if (node >= n) break;
        float2 acc = gather_sum(g2, node, lane);
        float di = g_dinv[node];
        float ox = di * acc.x + b.x;
        float oy = di * acc.y + b.y;
        int bg = batch[node];
        if (bg != curg) {
            if (curg >= 0) {
                atomicAdd(&g_psum[curg * 64 + 2 * lane], ps.x);
                atomicAdd(&g_psum[curg * 64 + 2 * lane + 1], ps.y);
            }
            ps = make_float2(0.f, 0.f);
            curg = bg;
        }
        ps.x += ox; ps.y += oy;
    }
    if (curg >= 0) {
        atomicAdd(&g_psum[curg * 64 + 2 * lane], ps.x);
        atomicAdd(&g_psum[curg * 64 + 2 * lane + 1], ps.y);
    }
}

// ---------------- final head: out[g][c] = (psum[g] @ Wl)/cnt + bl ----------------
__global__ void final_k(const float* __restrict__ Wl, const float* __restrict__ bl,
                        float* __restrict__ out) {
    int t = threadIdx.x;          // 128 threads = 64 graphs x 2 classes
    int g = t >> 1, c = t & 1;
    float s = 0.f;
    #pragma unroll
    for (int k = 0; k < 64; k++) s += g_psum[g * 64 + k] * Wl[k * 2 + c];
    int st = g_gstart[g], en = g_gend[g];
    float cnt = (en >= st) ? (float)(en - st + 1) : 0.f;
    out[t] = s / fmaxf(cnt, 1.f) + bl[c];
}

// ---------------- launch ----------------

extern "C" void kernel_launch(void* const* d_in, const int* in_sizes, int n_in,
                              void* d_out, int out_size) {
    const float* x     = (const float*)d_in[0];
    const int*   ei    = (const int*)d_in[1];
    const int*   batch = (const int*)d_in[2];
    const float* W1 = (const float*)d_in[3]; const float* b1 = (const float*)d_in[4];
    const float* W2 = (const float*)d_in[5]; const float* b2 = (const float*)d_in[6];
    const float* W3 = (const float*)d_in[7]; const float* b3 = (const float*)d_in[8];
    const float* Wl = (const float*)d_in[9]; const float* bl = (const float*)d_in[10];

    int n = in_sizes[0] / 64;
    int e = in_sizes[1] / 2;
    const int* src = ei;
    const int* dst = ei + e;

    int nb = (n + 1023) / 1024;
    int me = (e > n) ? e : n;
    int ntile = (n + GTM - 1) / GTM;

    __half *ga, *gb;
    cudaGetSymbolAddress((void**)&ga, g_ga);
    cudaGetSymbolAddress((void**)&gb, g_gb);

    xcvt_k  <<<(n * 8 + 255) / 256, 256>>>(x, n * 64);
    init_k  <<<(n + 255) / 256, 256>>>(n);
    countb_k<<<(me + 255) / 256, 256>>>(dst, batch, e, n);
    scan1_k <<<nb, 1024>>>(n);
    // gemm1 depends only on dinv + g_hbf; runs while CSR build finishes
    gemm_h2_k<<<ntile, 128>>>(W1, ga, n);
    scan2_k <<<1, 1024>>>(nb);
    scan3_k <<<nb, 1024>>>(n, e);
    fill_k  <<<(e + 255) / 256, 256>>>(src, dst, e);

    agggemm_k<<<ntile, 256>>>(b1, W2, ga, gb, n);
    agggemm_k<<<ntile, 256>>>(b2, W3, gb, ga, n);
    aggpool_k<<<ntile, 256>>>(b3, batch, ga, n);
    final_k  <<<1, 128>>>(Wl, bl, (float*)d_out);
}

// round 7
// speedup vs baseline: 1.2732x; 1.2732x over previous
#include <cuda_runtime.h>
#include <cuda_fp16.h>

typedef unsigned long long u64;
typedef unsigned int u32;

#define NMAX 100000
#define NPAD (NMAX + 128)
#define EMAX 1600000
#define NG   64
#define GTM  128   // rows per GEMM CTA

// ---- device scratch ----
__device__ __half g_ga[NPAD * 64];    // g buffers (double-buffered), fp16
__device__ __half g_gb[NPAD * 64];
__device__ __half g_hbf[NPAD * 64];   // activations fp16 (zero beyond n, never written there)
__device__ float  g_psum[NG * 64];    // pooled partial sums
__device__ float  g_dinv[NMAX];
__device__ int    g_cnt[NMAX];
__device__ int    g_rowptr[NMAX + 1];
__device__ int    g_cursor[NMAX];
__device__ int    g_col[EMAX];
__device__ int    g_bsums[1024];
__device__ int    g_gstart[NG];
__device__ int    g_gend[NG];

// ---------------- setup kernels ----------------

__global__ void init_k(int n) {
    int i = blockIdx.x * blockDim.x + threadIdx.x;
    if (i < n) g_cnt[i] = 0;
    if (i < NG) { g_gstart[i] = 0x7fffffff; g_gend[i] = -1; }
    if (i < NG * 64) g_psum[i] = 0.f;
}

// x (fp32) -> g_hbf (fp16)
__global__ void xcvt_k(const float* __restrict__ x, int n64) {
    int i = blockIdx.x * blockDim.x + threadIdx.x;   // 8 elems per thread
    if (i * 8 >= n64) return;
    const float4* xp = (const float4*)(x) + i * 2;
    float4 a = xp[0], b = xp[1];
    __half2 h0 = __floats2half2_rn(a.x, a.y);
    __half2 h1 = __floats2half2_rn(a.z, a.w);
    __half2 h2 = __floats2half2_rn(b.x, b.y);
    __half2 h3 = __floats2half2_rn(b.z, b.w);
    ((uint4*)g_hbf)[i] = make_uint4(*(u32*)&h0, *(u32*)&h1, *(u32*)&h2, *(u32*)&h3);
}

// degree count + graph bounds via sorted-batch boundary detection
__global__ void countb_k(const int* __restrict__ dst, const int* __restrict__ batch,
                         int e, int n) {
    int i = blockIdx.x * blockDim.x + threadIdx.x;
    if (i < e) atomicAdd(&g_cnt[dst[i]], 1);
    if (i < n) {
        int b = batch[i];
        if (i == 0) g_gstart[b] = 0;
        else {
            int pb = batch[i - 1];
            if (pb != b) { g_gstart[b] = i; g_gend[pb] = i - 1; }
        }
        if (i == n - 1) g_gend[b] = n - 1;
    }
}

__global__ void scan1_k(int n) {
    int t = threadIdx.x;
    int i = blockIdx.x * 1024 + t;
    int v = (i < n) ? g_cnt[i] : 0;
    if (i < n) g_dinv[i] = rsqrtf((float)v + 1.0f);
    int x = v;
    #pragma unroll
    for (int o = 1; o < 32; o <<= 1) {
        int y = __shfl_up_sync(0xffffffffu, x, o);
        if ((t & 31) >= o) x += y;
    }
    __shared__ int wsum[32];
    if ((t & 31) == 31) wsum[t >> 5] = x;
    __syncthreads();
    if (t < 32) {
        int y = wsum[t];
        int z = y;
        #pragma unroll
        for (int o = 1; o < 32; o <<= 1) {
            int w = __shfl_up_sync(0xffffffffu, z, o);
            if (t >= o) z += w;
        }
        wsum[t] = z - y;
        if (t == 31) g_bsums[blockIdx.x] = z;
    }
    __syncthreads();
    int excl = (x - v) + wsum[t >> 5];
    if (i < n) g_rowptr[i] = excl;
}

__global__ void scan2_k(int nb) {
    int t = threadIdx.x;
    int v = (t < nb) ? g_bsums[t] : 0;
    int x = v;
    #pragma unroll
    for (int o = 1; o < 32; o <<= 1) {
        int y = __shfl_up_sync(0xffffffffu, x, o);
        if ((t & 31) >= o) x += y;
    }
    __shared__ int wsum[32];
    if ((t & 31) == 31) wsum[t >> 5] = x;
    __syncthreads();
    if (t < 32) {
        int y = wsum[t];
        int z = y;
        #pragma unroll
        for (int o = 1; o < 32; o <<= 1) {
            int w = __shfl_up_sync(0xffffffffu, z, o);
            if (t >= o) z += w;
        }
        wsum[t] = z - y;
    }
    __syncthreads();
    int excl = (x - v) + wsum[t >> 5];
    if (t < nb) g_bsums[t] = excl;
}

__global__ void scan3_k(int n, int etot) {
    int i = blockIdx.x * 1024 + threadIdx.x;
    if (i < n) {
        int v = g_rowptr[i] + g_bsums[blockIdx.x];
        g_rowptr[i] = v;
        g_cursor[i] = v;
    }
    if (i == 0) g_rowptr[n] = etot;
}

__global__ void fill_k(const int* __restrict__ src, const int* __restrict__ dst, int e) {
    int i = blockIdx.x * blockDim.x + threadIdx.x;
    if (i < e) {
        int d = dst[i];
        int p = atomicAdd(&g_cursor[d], 1);
        g_col[p] = src[i];
    }
}

// ---- shared gather: fp32 edge-sum of g rows (half2 lane layout) ----
static __device__ __forceinline__ float2 gather_sum(const __half2* __restrict__ g2,
                                                    int node, int lane) {
    int beg = g_rowptr[node];
    int end = g_rowptr[node + 1];
    float2 acc = __half22float2(g2[(size_t)node * 32 + lane]);   // self term
    int e = beg;
    for (; e + 8 <= end; e += 8) {
        int s0 = __ldg(&g_col[e + 0]);
        int s1 = __ldg(&g_col[e + 1]);
        int s2 = __ldg(&g_col[e + 2]);
        int s3 = __ldg(&g_col[e + 3]);
        int s4 = __ldg(&g_col[e + 4]);
        int s5 = __ldg(&g_col[e + 5]);
        int s6 = __ldg(&g_col[e + 6]);
        int s7 = __ldg(&g_col[e + 7]);
        float2 f0 = __half22float2(g2[(size_t)s0 * 32 + lane]);
        float2 f1 = __half22float2(g2[(size_t)s1 * 32 + lane]);
        float2 f2 = __half22float2(g2[(size_t)s2 * 32 + lane]);
        float2 f3 = __half22float2(g2[(size_t)s3 * 32 + lane]);
        float2 f4 = __half22float2(g2[(size_t)s4 * 32 + lane]);
        float2 f5 = __half22float2(g2[(size_t)s5 * 32 + lane]);
        float2 f6 = __half22float2(g2[(size_t)s6 * 32 + lane]);
        float2 f7 = __half22float2(g2[(size_t)s7 * 32 + lane]);
        acc.x += ((f0.x + f1.x) + (f2.x + f3.x)) + ((f4.x + f5.x) + (f6.x + f7.x));
        acc.y += ((f0.y + f1.y) + (f2.y + f3.y)) + ((f4.y + f5.y) + (f6.y + f7.y));
    }
    for (; e < end; e++) {
        int s = __ldg(&g_col[e]);
        float2 v = __half22float2(g2[(size_t)s * 32 + lane]);
        acc.x += v.x; acc.y += v.y;
    }
    return acc;
}

// ---------------- HFMA2 GEMM (R5-proven) ----------------
// CTA: 128 rows x 64 cols, 128 threads; thread: 8 rows x 8 cols.
// gout[r] = fp16( dinv[r] * (g_hbf[r] @ W) ); tiles offset by tileoff.
__global__ void __launch_bounds__(128, 4) gemm_h2_k(const float* __restrict__ W,
                                                    __half* __restrict__ gout,
                                                    int tileoff, int n) {
    __shared__ __align__(16) unsigned char sXT[16384];   // 64 k x 128 halves (swizzled)
    __shared__ __align__(16) __half sWh[4096];           // w[k][c]
    __shared__ float sdinv[GTM];

    int t = threadIdx.x;
    int tile0 = (blockIdx.x + tileoff) * GTM;

    {
        const float4* W4 = (const float4*)W;
        __half2* wh2 = (__half2*)sWh;
        #pragma unroll
        for (int j = t; j < 1024; j += 128) {
            float4 v = W4[j];
            wh2[2 * j]     = __floats2half2_rn(v.x, v.y);
            wh2[2 * j + 1] = __floats2half2_rn(v.z, v.w);
        }
    }
    if (t < GTM) {
        int r = tile0 + t;
        sdinv[t] = (r < n) ? g_dinv[r] : 0.f;
    }
    {
        int r = t;
        const uint4* hp = (const uint4*)(g_hbf + (size_t)(tile0 + r) * 64);
        int rc = r >> 3, rb = (r & 7) * 2;
        #pragma unroll
        for (int q = 0; q < 8; q++) {
            uint4 v = hp[q];
            __half h[8];
            *(uint4*)h = v;
            #pragma unroll
            for (int j = 0; j < 8; j++) {
                int k = 8 * q + j;
                *(__half*)(sXT + k * 256 + ((rc ^ (k & 15)) << 4) + rb) = h[j];
            }
        }
    }
    __syncthreads();

    int rg = t & 15;
    int cgp = t >> 4;

    float fac[64];
    #pragma unroll
    for (int a = 0; a < 64; a++) fac[a] = 0.f;

    #pragma unroll
    for (int half = 0; half < 2; half++) {
        __half2 acc[32];
        #pragma unroll
        for (int a = 0; a < 32; a++) acc[a] = __floats2half2_rn(0.f, 0.f);

        #pragma unroll 8
        for (int kk = 0; kk < 32; kk++) {
            int k = half * 32 + kk;
            uint4 xv = *(const uint4*)(sXT + k * 256 + ((rg ^ (k & 15)) << 4));
            uint4 wv = *(const uint4*)(sWh + (size_t)k * 64 + cgp * 8);
            __half2 w0 = *(__half2*)&wv.x, w1 = *(__half2*)&wv.y;
            __half2 w2 = *(__half2*)&wv.z, w3 = *(__half2*)&wv.w;
            u32 xw[4] = {xv.x, xv.y, xv.z, xv.w};
            #pragma unroll
            for (int p = 0; p < 4; p++) {
                __half2 xpair = *(__half2*)&xw[p];
                __half2 xlo = __low2half2(xpair);
                __half2 xhi = __high2half2(xpair);
                acc[(2 * p) * 4 + 0] = __hfma2(xlo, w0, acc[(2 * p) * 4 + 0]);
                acc[(2 * p) * 4 + 1] = __hfma2(xlo, w1, acc[(2 * p) * 4 + 1]);
                acc[(2 * p) * 4 + 2] = __hfma2(xlo, w2, acc[(2 * p) * 4 + 2]);
                acc[(2 * p) * 4 + 3] = __hfma2(xlo, w3, acc[(2 * p) * 4 + 3]);
                acc[(2 * p + 1) * 4 + 0] = __hfma2(xhi, w0, acc[(2 * p + 1) * 4 + 0]);
                acc[(2 * p + 1) * 4 + 1] = __hfma2(xhi, w1, acc[(2 * p + 1) * 4 + 1]);
                acc[(2 * p + 1) * 4 + 2] = __hfma2(xhi, w2, acc[(2 * p + 1) * 4 + 2]);
                acc[(2 * p + 1) * 4 + 3] = __hfma2(xhi, w3, acc[(2 * p + 1) * 4 + 3]);
            }
        }
        #pragma unroll
        for (int j = 0; j < 8; j++)
            #pragma unroll
            for (int cp = 0; cp < 4; cp++) {
                float2 f = __half22float2(acc[j * 4 + cp]);
                fac[j * 8 + 2 * cp]     += f.x;
                fac[j * 8 + 2 * cp + 1] += f.y;
            }
    }

    #pragma unroll
    for (int j = 0; j < 8; j++) {
        int r = 8 * rg + j;
        int node = tile0 + r;
        if (node < n) {
            float di = sdinv[r];
            __half2 o[4];
            #pragma unroll
            for (int cp = 0; cp < 4; cp++)
                o[cp] = __floats2half2_rn(fac[j * 8 + 2 * cp] * di,
                                          fac[j * 8 + 2 * cp + 1] * di);
            ((uint4*)(gout + (size_t)node * 64))[cgp] = *(uint4*)o;
        }
    }
}

// ---------------- aggregation (one warp per node) ----------------
// h[i] = relu( dinv[i]*(sum g[j] + g[i]) + bias ), fp16 -> g_hbf; nodes [node0, node0+cnt)
__global__ void __launch_bounds__(256) agg64_k(const float* __restrict__ bias,
                                               const __half* __restrict__ gin,
                                               int node0, int cnt, int n) {
    int idx = (blockIdx.x * blockDim.x + threadIdx.x) >> 5;
    int lane = threadIdx.x & 31;
    if (idx >= cnt) return;
    int node = node0 + idx;
    if (node >= n) return;

    float2 acc = gather_sum((const __half2*)gin, node, lane);
    float di = g_dinv[node];
    float2 b = ((const float2*)bias)[lane];
    float ox = fmaxf(di * acc.x + b.x, 0.f);
    float oy = fmaxf(di * acc.y + b.y, 0.f);
    __half2 o2 = __floats2half2_rn(ox, oy);
    ((__half2*)g_hbf)[(size_t)node * 32 + lane] = o2;
}

// ---------------- fused agg (layer 3) + pool partial sums ----------------
// warp handles 8 consecutive nodes; per-graph fp32 partials flushed via spread atomics
__global__ void __launch_bounds__(256) aggpool_k(const float* __restrict__ bias,
                                                 const int* __restrict__ batch,
                                                 const __half* __restrict__ gin,
                                                 int node0, int cnt, int n) {
    int t = threadIdx.x;
    int w = t >> 5, lane = t & 31;
    int base = node0 + (blockIdx.x * 8 + w) * 8;
    float2 b = ((const float2*)bias)[lane];
    const __half2* g2 = (const __half2*)gin;

    float2 ps = make_float2(0.f, 0.f);
    int curg = -1;
    #pragma unroll 1
    for (int i = 0; i < 8; i++) {
        int node = base + i;
        if (node - node0 >= cnt || node >= n) break;
        float2 acc = gather_sum(g2, node, lane);
        float di = g_dinv[node];
        float ox = di * acc.x + b.x;
        float oy = di * acc.y + b.y;
        int bg = batch[node];
        if (bg != curg) {
            if (curg >= 0) {
                atomicAdd(&g_psum[curg * 64 + 2 * lane], ps.x);
                atomicAdd(&g_psum[curg * 64 + 2 * lane + 1], ps.y);
            }
            ps = make_float2(0.f, 0.f);
            curg = bg;
        }
        ps.x += ox; ps.y += oy;
    }
    if (curg >= 0) {
        atomicAdd(&g_psum[curg * 64 + 2 * lane], ps.x);
        atomicAdd(&g_psum[curg * 64 + 2 * lane + 1], ps.y);
    }
}

// ---------------- final head ----------------
__global__ void final_k(const float* __restrict__ Wl, const float* __restrict__ bl,
                        float* __restrict__ out) {
    int t = threadIdx.x;          // 128 threads = 64 graphs x 2 classes
    int g = t >> 1, c = t & 1;
    float s = 0.f;
    #pragma unroll
    for (int k = 0; k < 64; k++) s += g_psum[g * 64 + k] * Wl[k * 2 + c];
    int st = g_gstart[g], en = g_gend[g];
    float cntf = (en >= st) ? (float)(en - st + 1) : 0.f;
    out[t] = s / fmaxf(cntf, 1.f) + bl[c];
}

// ---------------- launch ----------------

extern "C" void kernel_launch(void* const* d_in, const int* in_sizes, int n_in,
                              void* d_out, int out_size) {
    const float* x     = (const float*)d_in[0];
    const int*   ei    = (const int*)d_in[1];
    const int*   batch = (const int*)d_in[2];
    const float* W1 = (const float*)d_in[3]; const float* b1 = (const float*)d_in[4];
    const float* W2 = (const float*)d_in[5]; const float* b2 = (const float*)d_in[6];
    const float* W3 = (const float*)d_in[7]; const float* b3 = (const float*)d_in[8];
    const float* Wl = (const float*)d_in[9]; const float* bl = (const float*)d_in[10];

    int n = in_sizes[0] / 64;
    int e = in_sizes[1] / 2;
    const int* src = ei;
    const int* dst = ei + e;

    int nb = (n + 1023) / 1024;
    int me = (e > n) ? e : n;
    int ntile = (n + GTM - 1) / GTM;
    int tilesA = (ntile + 1) / 2;          // first-half tiles
    int tilesB = ntile - tilesA;
    int nh = tilesA * GTM;                  // node split point (tile aligned)
    int cntA = (nh < n) ? nh : n;
    int cntB = n - cntA;

    __half *ga, *gb;
    cudaGetSymbolAddress((void**)&ga, g_ga);
    cudaGetSymbolAddress((void**)&gb, g_gb);

    // second stream + fork/join events (created per call; never destroyed while capturing)
    cudaStream_t sB;
    cudaStreamCreateWithFlags(&sB, cudaStreamNonBlocking);
    cudaEvent_t e0, eD, eF, eA1, eG2, eA2, eG3;
    cudaEventCreateWithFlags(&e0,  cudaEventDisableTiming);
    cudaEventCreateWithFlags(&eD,  cudaEventDisableTiming);
    cudaEventCreateWithFlags(&eF,  cudaEventDisableTiming);
    cudaEventCreateWithFlags(&eA1, cudaEventDisableTiming);
    cudaEventCreateWithFlags(&eG2, cudaEventDisableTiming);
    cudaEventCreateWithFlags(&eA2, cudaEventDisableTiming);
    cudaEventCreateWithFlags(&eG3, cudaEventDisableTiming);

    // fork
    cudaEventRecord(e0, 0);
    cudaStreamWaitEvent(sB, e0, 0);

    // stream 0: x -> fp16
    xcvt_k<<<(n * 8 + 255) / 256, 256>>>(x, n * 64);

    // stream B: CSR build
    init_k  <<<(n + 255) / 256, 256, 0, sB>>>(n);
    countb_k<<<(me + 255) / 256, 256, 0, sB>>>(dst, batch, e, n);
    scan1_k <<<nb, 1024, 0, sB>>>(n);
    cudaEventRecord(eD, sB);                       // dinv ready
    scan2_k <<<1, 1024, 0, sB>>>(nb);
    scan3_k <<<nb, 1024, 0, sB>>>(n, e);
    fill_k  <<<(e + 255) / 256, 256, 0, sB>>>(src, dst, e);
    cudaEventRecord(eF, sB);                       // CSR ready

    // stream 0: gemm1 (needs dinv only) overlaps scan2/scan3/fill
    cudaStreamWaitEvent(0, eD, 0);
    gemm_h2_k<<<ntile, 128>>>(W1, ga, 0, n);

    // layer 1 agg, half A
    cudaStreamWaitEvent(0, eF, 0);
    agg64_k<<<(cntA + 7) / 8, 256>>>(b1, ga, 0, cntA, n);
    cudaEventRecord(eA1, 0);

    // sB: gemm2 half A (reads h[0,nh) + writes gb) concurrent with agg1b+gemm2b on 0
    cudaStreamWaitEvent(sB, eA1, 0);
    gemm_h2_k<<<tilesA, 128, 0, sB>>>(W2, gb, 0, n);
    cudaEventRecord(eG2, sB);

    // stream 0: agg1 half B, then gemm2 half B
    agg64_k<<<(cntB + 7) / 8, 256>>>(b1, ga, cntA, cntB, n);
    gemm_h2_k<<<tilesB, 128>>>(W2, gb, tilesA, n);

    // layer 2 agg half A (needs full gemm2)
    cudaStreamWaitEvent(0, eG2, 0);
    agg64_k<<<(cntA + 7) / 8, 256>>>(b2, gb, 0, cntA, n);
    cudaEventRecord(eA2, 0);

    // sB: gemm3 half A concurrent with agg2b+gemm3b on 0
    cudaStreamWaitEvent(sB, eA2, 0);
    gemm_h2_k<<<tilesA, 128, 0, sB>>>(W3, ga, 0, n);
    cudaEventRecord(eG3, sB);

    // stream 0: agg2 half B, gemm3 half B
    agg64_k<<<(cntB + 7) / 8, 256>>>(b2, gb, cntA, cntB, n);
    gemm_h2_k<<<tilesB, 128>>>(W3, ga, tilesA, n);

    // layer 3 agg + pool (needs full gemm3)
    cudaStreamWaitEvent(0, eG3, 0);
    aggpool_k<<<(n + 63) / 64, 256>>>(b3, batch, ga, 0, n, n);
    final_k<<<1, 128>>>(Wl, bl, (float*)d_out);
}